// round 8
// baseline (speedup 1.0000x reference)
#include <cuda_runtime.h>
#include <cstdint>

#define NBATCH 4
#define LRES   256
#define NATOM  14
#define FEAT   128
#define MPAIR  196      // NATOM*NATOM
#define MAXAA  22
#define NAPAIR 484      // MAXAA*MAXAA
#define NREL   65
#define TPAIR  128      // pairs per block tile (8 i-rows x 16 j-cols)
#define NTHREADS 256

typedef unsigned long long ull;

// ---------------- scratch (static __device__ — no allocations allowed) ----------------
__device__ float g_softc[NAPAIR * MPAIR];          // softplus(distcoef_embed)
__device__ float g_preA [NAPAIR * FEAT];           // aa_pair_embed @ out_w1[0:128]
__device__ float g_preR [NREL   * FEAT];           // relpos_embed  @ out_w1[128:256]
__device__ float g_dihed[NBATCH * LRES * LRES * 2];// (phi, psi) per pair

// ---------------- packed f32x2 helpers ----------------
__device__ __forceinline__ ull pack2(float lo, float hi) {
    ull r; asm("mov.b64 %0, {%1, %2};" : "=l"(r) : "f"(lo), "f"(hi)); return r;
}
__device__ __forceinline__ void fma2(ull& d, ull a, ull b) {
    asm("fma.rn.f32x2 %0, %1, %2, %0;" : "+l"(d) : "l"(a), "l"(b));
}
__device__ __forceinline__ float2 unpack2(ull v) {
    float2 r; asm("mov.b64 {%0, %1}, %2;" : "=f"(r.x), "=f"(r.y) : "l"(v)); return r;
}

// ---------------- small precompute kernels ----------------
__global__ void softc_kernel(const float* __restrict__ distcoef) {
    int idx = blockIdx.x * 256 + threadIdx.x;
    if (idx < NAPAIR * MPAIR) {
        float x = distcoef[idx];
        g_softc[idx] = (x > 20.f) ? x : log1pf(expf(x));
    }
}

__global__ void pretab_kernel(const float* __restrict__ aa_pair_embed,
                              const float* __restrict__ relpos_embed,
                              const float* __restrict__ ow1) {
    __shared__ float e[FEAT];
    int b = blockIdx.x, f = threadIdx.x;
    if (b < NAPAIR) {
        e[f] = aa_pair_embed[b * FEAT + f];
        __syncthreads();
        float acc = 0.f;
        #pragma unroll 8
        for (int k = 0; k < FEAT; k++) acc += e[k] * ow1[k * FEAT + f];
        g_preA[b * FEAT + f] = acc;
    } else {
        int r = b - NAPAIR;
        e[f] = relpos_embed[r * FEAT + f];
        __syncthreads();
        float acc = 0.f;
        #pragma unroll 8
        for (int k = 0; k < FEAT; k++) acc += e[k] * ow1[(FEAT + k) * FEAT + f];
        g_preR[r * FEAT + f] = acc;
    }
}

__device__ __forceinline__ float3 f3sub(float3 a, float3 b) { return make_float3(a.x-b.x, a.y-b.y, a.z-b.z); }
__device__ __forceinline__ float3 f3cross(float3 a, float3 b) {
    return make_float3(a.y*b.z - a.z*b.y, a.z*b.x - a.x*b.z, a.x*b.y - a.y*b.x);
}
__device__ __forceinline__ float f3dot(float3 a, float3 b) { return a.x*b.x + a.y*b.y + a.z*b.z; }

__device__ __forceinline__ float dihedral_f(float3 p0, float3 p1, float3 p2, float3 p3) {
    float3 v0 = f3sub(p2, p1), v1 = f3sub(p0, p1), v2 = f3sub(p3, p2);
    float3 u1 = f3cross(v0, v1), u2 = f3cross(v0, v2);
    float nn = f3dot(u1, u1) * f3dot(u2, u2);
    if (!(nn > 0.f)) return 0.f;
    float cosv = f3dot(u1, u2) * rsqrtf(nn);
    cosv = fminf(fmaxf(cosv, -0.999999f), 0.999999f);
    float sd = f3dot(f3cross(v1, v2), v0);
    float sgn = (sd > 0.f) ? 1.f : ((sd < 0.f) ? -1.f : 0.f);
    float d = sgn * acosf(cosv);
    return isfinite(d) ? d : 0.f;
}

__global__ void dihed_kernel(const float* __restrict__ pos) {
    int idx = blockIdx.x * 256 + threadIdx.x;        // NB*L*L threads exactly
    int n = idx >> 16, i = (idx >> 8) & 255, j = idx & 255;
    const float* pi = pos + (size_t)(n * LRES + i) * NATOM * 3;
    const float* pj = pos + (size_t)(n * LRES + j) * NATOM * 3;
    float3 Ni  = make_float3(pi[0], pi[1], pi[2]);
    float3 CAi = make_float3(pi[3], pi[4], pi[5]);
    float3 Ci  = make_float3(pi[6], pi[7], pi[8]);
    float3 Nj  = make_float3(pj[0], pj[1], pj[2]);
    float3 CAj = make_float3(pj[3], pj[4], pj[5]);
    float3 Cj  = make_float3(pj[6], pj[7], pj[8]);
    float phi = dihedral_f(Ci, Nj, CAj, Cj);
    float psi = dihedral_f(Ni, CAi, Ci, Nj);
    g_dihed[(size_t)idx * 2 + 0] = phi;
    g_dihed[(size_t)idx * 2 + 1] = psi;
}

// ---------------- fused main kernel ----------------
// Tile: 128 pairs (8 i x 16 j) x 128 feat. 8 warps, 256 threads.
// warp -> 16-feature slice [warp*16, warp*16+16). Each warp covers ALL 128
// pairs: thread owns pairs lane+32q (q=0..3), acc[q][8] packed-f32x2 over f.
struct __align__(16) Smem {
    float bufG[MPAIR * TPAIR];  // 100.4KB: stage1 act G; reused later
    float bufB[FEAT * TPAIR];   // 64KB ping-pong
    float sW[32 * FEAT];        // 16KB weight chunk
    float wdh[26 * FEAT];       // 13KB dihedral weight rows of out_w1
    float dcode[TPAIR * 26];    // 13.3KB
    float posI[8 * NATOM * 3];
    float posJ[16 * NATOM * 3];
    float maskI[8 * NATOM];
    float maskJ[16 * NATOM];
    float b1[FEAT]; float b2[FEAT]; float b3[FEAT]; float b4[FEAT]; float b5[FEAT];
    float sc[TPAIR]; float mp[TPAIR];
    int aap[TPAIR]; int rel[TPAIR];
    int aaI[8]; int aaJ[16]; int resI[8]; int resJ[16]; int chI[8]; int chJ[16];
};

// acc[q][t] covers pair (lane+32q), features (fbase+2t, fbase+2t+1).
// Weight chunks double-buffered through registers.
template<int K>
__device__ __forceinline__ void gemm_acc(const float* __restrict__ Wg,
                                         const float* __restrict__ sAct,
                                         float* __restrict__ sW,
                                         ull acc[4][8],
                                         int tid, int lane, int fbase) {
    constexpr int NCH = (K + 31) / 32;
    float4 r0, r1, r2, r3;
    {   // prefetch chunk 0 (32x128 floats = 1024 float4, 256 threads -> 4 each)
        const float4* src = (const float4*)Wg;
        constexpr int lim = (K < 32 ? K : 32) * 32;
        if (tid < lim)       r0 = src[tid];
        if (tid + 256 < lim) r1 = src[tid + 256];
        if (tid + 512 < lim) r2 = src[tid + 512];
        if (tid + 768 < lim) r3 = src[tid + 768];
    }
    #pragma unroll 1
    for (int c = 0; c < NCH; c++) {
        const int k0 = c * 32;
        const int rows = (K - k0 < 32) ? (K - k0) : 32;
        __syncthreads();
        {   // commit prefetched chunk to smem
            float4* dst = (float4*)sW;
            const int lim = rows * 32;
            if (tid < lim)       dst[tid] = r0;
            if (tid + 256 < lim) dst[tid + 256] = r1;
            if (tid + 512 < lim) dst[tid + 512] = r2;
            if (tid + 768 < lim) dst[tid + 768] = r3;
        }
        if (c + 1 < NCH) {  // prefetch next chunk
            const float4* src = (const float4*)(Wg + (k0 + 32) * FEAT);
            const int lim = ((K - k0 - 32 < 32) ? (K - k0 - 32) : 32) * 32;
            if (tid < lim)       r0 = src[tid];
            if (tid + 256 < lim) r1 = src[tid + 256];
            if (tid + 512 < lim) r2 = src[tid + 512];
            if (tid + 768 < lim) r3 = src[tid + 768];
        }
        __syncthreads();
        if (rows == 32) {
            #pragma unroll 4
            for (int kk = 0; kk < 32; kk++) {
                const float* arow = sAct + (k0 + kk) * TPAIR + lane;
                float a0 = arow[0], a1 = arow[32], a2 = arow[64], a3 = arow[96];
                ull av0 = pack2(a0, a0), av1 = pack2(a1, a1);
                ull av2 = pack2(a2, a2), av3 = pack2(a3, a3);
                const ulonglong2* wr = (const ulonglong2*)(sW + kk * FEAT + fbase);
                #pragma unroll
                for (int m = 0; m < 4; m++) {
                    ulonglong2 w2 = wr[m];
                    fma2(acc[0][2 * m],     av0, w2.x);
                    fma2(acc[0][2 * m + 1], av0, w2.y);
                    fma2(acc[1][2 * m],     av1, w2.x);
                    fma2(acc[1][2 * m + 1], av1, w2.y);
                    fma2(acc[2][2 * m],     av2, w2.x);
                    fma2(acc[2][2 * m + 1], av2, w2.y);
                    fma2(acc[3][2 * m],     av3, w2.x);
                    fma2(acc[3][2 * m + 1], av3, w2.y);
                }
            }
        } else {
            for (int kk = 0; kk < rows; kk++) {
                const float* arow = sAct + (k0 + kk) * TPAIR + lane;
                float a0 = arow[0], a1 = arow[32], a2 = arow[64], a3 = arow[96];
                ull av0 = pack2(a0, a0), av1 = pack2(a1, a1);
                ull av2 = pack2(a2, a2), av3 = pack2(a3, a3);
                const ulonglong2* wr = (const ulonglong2*)(sW + kk * FEAT + fbase);
                #pragma unroll
                for (int m = 0; m < 4; m++) {
                    ulonglong2 w2 = wr[m];
                    fma2(acc[0][2 * m],     av0, w2.x);
                    fma2(acc[0][2 * m + 1], av0, w2.y);
                    fma2(acc[1][2 * m],     av1, w2.x);
                    fma2(acc[1][2 * m + 1], av1, w2.y);
                    fma2(acc[2][2 * m],     av2, w2.x);
                    fma2(acc[2][2 * m + 1], av2, w2.y);
                    fma2(acc[3][2 * m],     av3, w2.x);
                    fma2(acc[3][2 * m + 1], av3, w2.y);
                }
            }
        }
    }
}

// relu(acc + bias) -> dst in k-major layout dst[f][p]
__device__ __forceinline__ void epilogue(ull acc[4][8],
                                         const float* __restrict__ bias,
                                         float* __restrict__ dst, int lane, int fbase) {
    #pragma unroll
    for (int t = 0; t < 8; t++) {
        int f = fbase + 2 * t;
        float bx = bias[f], by = bias[f + 1];
        #pragma unroll
        for (int q = 0; q < 4; q++) {
            float2 v = unpack2(acc[q][t]);
            int p = lane + 32 * q;
            dst[f * TPAIR + p]       = fmaxf(v.x + bx, 0.f);
            dst[(f + 1) * TPAIR + p] = fmaxf(v.y + by, 0.f);
        }
    }
}

__global__ void __launch_bounds__(NTHREADS, 1)
fused_kernel(const int* __restrict__ aa, const int* __restrict__ res_nb,
             const int* __restrict__ chain_nb, const float* __restrict__ pos,
             const float* __restrict__ mask,
             const float* __restrict__ dw1, const float* __restrict__ db1,
             const float* __restrict__ dw2, const float* __restrict__ db2,
             const float* __restrict__ ow1, const float* __restrict__ ob1,
             const float* __restrict__ ow2, const float* __restrict__ ob2,
             const float* __restrict__ ow3, const float* __restrict__ ob3,
             float* __restrict__ outp) {
    extern __shared__ char smem_raw[];
    Smem& s = *reinterpret_cast<Smem*>(smem_raw);
    const int tid = threadIdx.x;
    const int warp = tid >> 5, lane = tid & 31;
    const int fbase = warp * 16;
    const int bid = blockIdx.x;
    const int n  = bid >> 9;                 // 32*16 tiles per batch
    const int i0 = ((bid >> 4) & 31) * 8;
    const int j0 = (bid & 15) * 16;

    // ---- phase 0: cooperative loads (256-thread strided, full coverage) ----
    {
        const float* pbI = pos + (size_t)(n * LRES + i0) * NATOM * 3;
        const float* pbJ = pos + (size_t)(n * LRES + j0) * NATOM * 3;
        for (int idx = tid; idx < 8 * NATOM * 3; idx += NTHREADS)  s.posI[idx] = pbI[idx];
        for (int idx = tid; idx < 16 * NATOM * 3; idx += NTHREADS) s.posJ[idx] = pbJ[idx];
        const float* mbI = mask + (size_t)(n * LRES + i0) * NATOM;
        const float* mbJ = mask + (size_t)(n * LRES + j0) * NATOM;
        if (tid < 8 * NATOM)  s.maskI[tid] = mbI[tid];
        if (tid < 16 * NATOM) s.maskJ[tid] = mbJ[tid];
        if (tid < 8) {
            s.aaI[tid]  = aa[n * LRES + i0 + tid];
            s.resI[tid] = res_nb[n * LRES + i0 + tid];
            s.chI[tid]  = chain_nb[n * LRES + i0 + tid];
        }
        if (tid >= 32 && tid < 48) {
            int t = tid - 32;
            s.aaJ[t]  = aa[n * LRES + j0 + t];
            s.resJ[t] = res_nb[n * LRES + j0 + t];
            s.chJ[t]  = chain_nb[n * LRES + j0 + t];
        }
        if (tid >= 64 && tid < 192) {
            int t = tid - 64;
            s.b1[t] = db1[t]; s.b2[t] = db2[t]; s.b3[t] = ob1[t];
            s.b4[t] = ob2[t]; s.b5[t] = ob3[t];
        }
        for (int idx = tid; idx < 26 * FEAT; idx += NTHREADS) s.wdh[idx] = ow1[384 * FEAT + idx];
    }
    __syncthreads();

    // ---- phase 0b: per-pair meta + dihedral angular codes ----
    if (tid < TPAIR) {
        int ii = tid >> 4, jj = tid & 15;
        s.aap[tid] = s.aaI[ii] * MAXAA + s.aaJ[jj];
        int r = s.resI[ii] - s.resJ[jj];
        s.rel[tid] = min(max(r, -32), 32) + 32;
        s.sc[tid] = (s.chI[ii] == s.chJ[jj]) ? 1.f : 0.f;
        s.mp[tid] = s.maskI[ii * NATOM + 1] * s.maskJ[jj * NATOM + 1];   // CA masks
        const float* dh = &g_dihed[((size_t)(n * LRES + i0 + ii) * LRES + (j0 + jj)) * 2];
        float phi = dh[0], psi = dh[1];
        float* c = &s.dcode[tid * 26];
        const float FRQ[6] = {1.f, 2.f, 3.f, 1.f, 0.5f, 1.f / 3.f};
        c[0] = phi; c[13] = psi;
        #pragma unroll
        for (int t = 0; t < 6; t++) {
            float sv, cv;
            sincosf(phi * FRQ[t], &sv, &cv); c[1 + t]  = sv; c[7 + t]  = cv;
            sincosf(psi * FRQ[t], &sv, &cv); c[14 + t] = sv; c[20 + t] = cv;
        }
    }
    __syncthreads();

    // ---- phase 1: masked gaussian distance features, k-major G[m][p] ----
    for (int idx = tid; idx < TPAIR * MPAIR; idx += NTHREADS) {
        int m = idx >> 7;
        int pp = idx & (TPAIR - 1);
        int a = m / NATOM;
        int b = m - a * NATOM;
        int ii = pp >> 4, jj = pp & 15;
        float dx = s.posI[ii * 42 + a * 3 + 0] - s.posJ[jj * 42 + b * 3 + 0];
        float dy = s.posI[ii * 42 + a * 3 + 1] - s.posJ[jj * 42 + b * 3 + 1];
        float dz = s.posI[ii * 42 + a * 3 + 2] - s.posJ[jj * 42 + b * 3 + 2];
        float ss = dx * dx + dy * dy + dz * dz;        // (10*d)^2
        float cc = g_softc[s.aap[pp] * MPAIR + m];
        float g = __expf(-cc * ss * 0.01f) * (s.maskI[ii * NATOM + a] * s.maskJ[jj * NATOM + b]);
        s.bufG[idx] = g;
    }
    // gemm's leading __syncthreads covers bufG visibility

    ull acc[4][8];

    // ---- stage 1: h1 = relu(G @ dist_w1 + b1) -> bufB ----
    #pragma unroll
    for (int q = 0; q < 4; q++)
        #pragma unroll
        for (int t = 0; t < 8; t++) acc[q][t] = 0ull;
    gemm_acc<MPAIR>(dw1, s.bufG, s.sW, acc, tid, lane, fbase);
    epilogue(acc, s.b1, s.bufB, lane, fbase);

    // ---- stage 2: fd = relu(h1 @ dist_w2 + b2) -> bufG ----
    #pragma unroll
    for (int q = 0; q < 4; q++)
        #pragma unroll
        for (int t = 0; t < 8; t++) acc[q][t] = 0ull;
    gemm_acc<FEAT>(dw2, s.bufB, s.sW, acc, tid, lane, fbase);
    epilogue(acc, s.b2, s.bufG, lane, fbase);

    // ---- stage 3: h = relu(preA + sc*preR + dihed@Wdh + fd@Wdist + ob1) -> bufB ----
    {
        #pragma unroll
        for (int q = 0; q < 4; q++) {
            int p = lane + 32 * q;
            int ap = s.aap[p], rl = s.rel[p];
            float scv = s.sc[p];
            const float4* A4 = (const float4*)&g_preA[ap * FEAT + fbase];
            const float4* R4 = (const float4*)&g_preR[rl * FEAT + fbase];
            #pragma unroll
            for (int m = 0; m < 4; m++) {
                float4 a4 = A4[m], r4 = R4[m];
                acc[q][2 * m]     = pack2(a4.x + scv * r4.x, a4.y + scv * r4.y);
                acc[q][2 * m + 1] = pack2(a4.z + scv * r4.z, a4.w + scv * r4.w);
            }
        }
        #pragma unroll 2
        for (int t = 0; t < 26; t++) {
            ull av0, av1, av2, av3;
            { float d = s.dcode[(lane)      * 26 + t]; av0 = pack2(d, d); }
            { float d = s.dcode[(lane + 32) * 26 + t]; av1 = pack2(d, d); }
            { float d = s.dcode[(lane + 64) * 26 + t]; av2 = pack2(d, d); }
            { float d = s.dcode[(lane + 96) * 26 + t]; av3 = pack2(d, d); }
            const ulonglong2* wr = (const ulonglong2*)(s.wdh + t * FEAT + fbase);
            #pragma unroll
            for (int m = 0; m < 4; m++) {
                ulonglong2 w2 = wr[m];
                fma2(acc[0][2 * m],     av0, w2.x);
                fma2(acc[0][2 * m + 1], av0, w2.y);
                fma2(acc[1][2 * m],     av1, w2.x);
                fma2(acc[1][2 * m + 1], av1, w2.y);
                fma2(acc[2][2 * m],     av2, w2.x);
                fma2(acc[2][2 * m + 1], av2, w2.y);
                fma2(acc[3][2 * m],     av3, w2.x);
                fma2(acc[3][2 * m + 1], av3, w2.y);
            }
        }
    }
    gemm_acc<FEAT>(ow1 + 256 * FEAT, s.bufG, s.sW, acc, tid, lane, fbase);
    epilogue(acc, s.b3, s.bufB, lane, fbase);

    // ---- stage 4: h = relu(h @ out_w2 + ob2) -> bufG ----
    #pragma unroll
    for (int q = 0; q < 4; q++)
        #pragma unroll
        for (int t = 0; t < 8; t++) acc[q][t] = 0ull;
    gemm_acc<FEAT>(ow2, s.bufB, s.sW, acc, tid, lane, fbase);
    epilogue(acc, s.b4, s.bufG, lane, fbase);

    // ---- stage 5: out = (h @ out_w3 + ob3) * mask_pair -> global ----
    #pragma unroll
    for (int q = 0; q < 4; q++)
        #pragma unroll
        for (int t = 0; t < 8; t++) acc[q][t] = 0ull;
    gemm_acc<FEAT>(ow3, s.bufG, s.sW, acc, tid, lane, fbase);
    #pragma unroll
    for (int q = 0; q < 4; q++) {
        int p = lane + 32 * q;
        int ii = p >> 4, jj = p & 15;
        float mpv = s.mp[p];
        float* orow = outp + ((((size_t)n * LRES + (i0 + ii)) * LRES + (j0 + jj)) * FEAT + fbase);
        #pragma unroll
        for (int m = 0; m < 4; m++) {
            float2 v0 = unpack2(acc[q][2 * m]);
            float2 v1 = unpack2(acc[q][2 * m + 1]);
            int f = fbase + 4 * m;
            float4 o = make_float4((v0.x + s.b5[f])     * mpv,
                                   (v0.y + s.b5[f + 1]) * mpv,
                                   (v1.x + s.b5[f + 2]) * mpv,
                                   (v1.y + s.b5[f + 3]) * mpv);
            *(float4*)&orow[4 * m] = o;
        }
    }
}

// ---------------- launch ----------------
extern "C" void kernel_launch(void* const* d_in, const int* in_sizes, int n_in,
                              void* d_out, int out_size) {
    const int*   aa        = (const int*)  d_in[0];
    const int*   res_nb    = (const int*)  d_in[1];
    const int*   chain_nb  = (const int*)  d_in[2];
    const float* pos       = (const float*)d_in[3];
    const float* mask      = (const float*)d_in[4];
    const float* aap_embed = (const float*)d_in[5];
    const float* rel_embed = (const float*)d_in[6];
    const float* distcoef  = (const float*)d_in[7];
    const float* dw1 = (const float*)d_in[8];
    const float* db1 = (const float*)d_in[9];
    const float* dw2 = (const float*)d_in[10];
    const float* db2 = (const float*)d_in[11];
    const float* ow1 = (const float*)d_in[12];
    const float* ob1 = (const float*)d_in[13];
    const float* ow2 = (const float*)d_in[14];
    const float* ob2 = (const float*)d_in[15];
    const float* ow3 = (const float*)d_in[16];
    const float* ob3 = (const float*)d_in[17];
    float* outp = (float*)d_out;

    cudaFuncSetAttribute(fused_kernel, cudaFuncAttributeMaxDynamicSharedMemorySize,
                         (int)sizeof(Smem));

    softc_kernel<<<(NAPAIR * MPAIR + 255) / 256, 256>>>(distcoef);
    pretab_kernel<<<NAPAIR + NREL, 128>>>(aap_embed, rel_embed, ow1);
    dihed_kernel<<<(NBATCH * LRES * LRES) / 256, 256>>>(pos);
    fused_kernel<<<NBATCH * 32 * 16, NTHREADS, sizeof(Smem)>>>(
        aa, res_nb, chain_nb, pos, mask,
        dw1, db1, dw2, db2, ow1, ob1, ow2, ob2, ow3, ob3, outp);
}

// round 9
// speedup vs baseline: 1.0970x; 1.0970x over previous
#include <cuda_runtime.h>
#include <cstdint>

#define NBATCH 4
#define LRES   256
#define NATOM  14
#define FEAT   128
#define MPAIR  196      // NATOM*NATOM
#define MAXAA  22
#define NAPAIR 484      // MAXAA*MAXAA
#define NREL   65
#define TPAIR  128      // pairs per block tile (8 i-rows x 16 j-cols)
#define NTHREADS 512
#define K3     154      // stage-3 K: 128 dist + 26 dihedral (contiguous ow1 rows 256..409)

typedef unsigned long long ull;

// ---------------- scratch (static __device__ — no allocations allowed) ----------------
__device__ float g_softc[NAPAIR * MPAIR];          // softplus(distcoef_embed)
__device__ float g_preA [NAPAIR * FEAT];           // aa_pair_embed @ out_w1[0:128]
__device__ float g_preR [NREL   * FEAT];           // relpos_embed  @ out_w1[128:256]
__device__ float g_dihed[NBATCH * LRES * LRES * 2];// (phi, psi) per pair

// ---------------- packed f32x2 helpers ----------------
__device__ __forceinline__ ull pack2(float lo, float hi) {
    ull r; asm("mov.b64 %0, {%1, %2};" : "=l"(r) : "f"(lo), "f"(hi)); return r;
}
__device__ __forceinline__ void fma2(ull& d, ull a, ull b) {
    asm("fma.rn.f32x2 %0, %1, %2, %0;" : "+l"(d) : "l"(a), "l"(b));
}
__device__ __forceinline__ float2 unpack2(ull v) {
    float2 r; asm("mov.b64 {%0, %1}, %2;" : "=f"(r.x), "=f"(r.y) : "l"(v)); return r;
}

// ---------------- small precompute kernels ----------------
__global__ void softc_kernel(const float* __restrict__ distcoef) {
    int idx = blockIdx.x * 256 + threadIdx.x;
    if (idx < NAPAIR * MPAIR) {
        float x = distcoef[idx];
        g_softc[idx] = (x > 20.f) ? x : log1pf(expf(x));
    }
}

__global__ void pretab_kernel(const float* __restrict__ aa_pair_embed,
                              const float* __restrict__ relpos_embed,
                              const float* __restrict__ ow1) {
    __shared__ float e[FEAT];
    int b = blockIdx.x, f = threadIdx.x;
    if (b < NAPAIR) {
        e[f] = aa_pair_embed[b * FEAT + f];
        __syncthreads();
        float acc = 0.f;
        #pragma unroll 8
        for (int k = 0; k < FEAT; k++) acc += e[k] * ow1[k * FEAT + f];
        g_preA[b * FEAT + f] = acc;
    } else {
        int r = b - NAPAIR;
        e[f] = relpos_embed[r * FEAT + f];
        __syncthreads();
        float acc = 0.f;
        #pragma unroll 8
        for (int k = 0; k < FEAT; k++) acc += e[k] * ow1[(FEAT + k) * FEAT + f];
        g_preR[r * FEAT + f] = acc;
    }
}

__device__ __forceinline__ float3 f3sub(float3 a, float3 b) { return make_float3(a.x-b.x, a.y-b.y, a.z-b.z); }
__device__ __forceinline__ float3 f3cross(float3 a, float3 b) {
    return make_float3(a.y*b.z - a.z*b.y, a.z*b.x - a.x*b.z, a.x*b.y - a.y*b.x);
}
__device__ __forceinline__ float f3dot(float3 a, float3 b) { return a.x*b.x + a.y*b.y + a.z*b.z; }

__device__ __forceinline__ float dihedral_f(float3 p0, float3 p1, float3 p2, float3 p3) {
    float3 v0 = f3sub(p2, p1), v1 = f3sub(p0, p1), v2 = f3sub(p3, p2);
    float3 u1 = f3cross(v0, v1), u2 = f3cross(v0, v2);
    float nn = f3dot(u1, u1) * f3dot(u2, u2);
    if (!(nn > 0.f)) return 0.f;
    float cosv = f3dot(u1, u2) * rsqrtf(nn);
    cosv = fminf(fmaxf(cosv, -0.999999f), 0.999999f);
    float sd = f3dot(f3cross(v1, v2), v0);
    float sgn = (sd > 0.f) ? 1.f : ((sd < 0.f) ? -1.f : 0.f);
    float d = sgn * acosf(cosv);
    return isfinite(d) ? d : 0.f;
}

__global__ void dihed_kernel(const float* __restrict__ pos) {
    int idx = blockIdx.x * 256 + threadIdx.x;        // NB*L*L threads exactly
    int n = idx >> 16, i = (idx >> 8) & 255, j = idx & 255;
    const float* pi = pos + (size_t)(n * LRES + i) * NATOM * 3;
    const float* pj = pos + (size_t)(n * LRES + j) * NATOM * 3;
    float3 Ni  = make_float3(pi[0], pi[1], pi[2]);
    float3 CAi = make_float3(pi[3], pi[4], pi[5]);
    float3 Ci  = make_float3(pi[6], pi[7], pi[8]);
    float3 Nj  = make_float3(pj[0], pj[1], pj[2]);
    float3 CAj = make_float3(pj[3], pj[4], pj[5]);
    float3 Cj  = make_float3(pj[6], pj[7], pj[8]);
    float phi = dihedral_f(Ci, Nj, CAj, Cj);
    float psi = dihedral_f(Ni, CAi, Ci, Nj);
    g_dihed[(size_t)idx * 2 + 0] = phi;
    g_dihed[(size_t)idx * 2 + 1] = psi;
}

// ---------------- fused main kernel ----------------
// Tile: 128 pairs (8 i x 16 j) x 128 feat. 16 warps, 512 threads.
// warp -> 8-feature slice [warp*8, warp*8+8). Each warp covers ALL 128 pairs:
// thread owns pairs lane+32q (q=0..3), acc[q][4] packed-f32x2 over features.
struct __align__(16) Smem {
    float bufG[MPAIR * TPAIR];  // 100.4KB: stage1 act; rows 0..153 = stage3 act
    float bufB[FEAT * TPAIR];   // 64KB ping-pong
    float sW[2][32 * FEAT];     // 32KB double-buffered weight chunks
    float dcodeK[26 * TPAIR];   // 13.3KB dihedral codes, k-major [t][p]
    float posI[8 * NATOM * 3];
    float posJ[16 * NATOM * 3];
    float maskI[8 * NATOM];
    float maskJ[16 * NATOM];
    float b1[FEAT]; float b2[FEAT]; float b3[FEAT]; float b4[FEAT]; float b5[FEAT];
    float sc[TPAIR]; float mp[TPAIR];
    int aap[TPAIR]; int rel[TPAIR];
    int aaI[8]; int aaJ[16]; int resI[8]; int resJ[16]; int chI[8]; int chJ[16];
};

// acc[q][t]: pair lane+32q, features (fbase+2t, fbase+2t+1), t=0..3.
// Weight chunks: smem double-buffer, ONE __syncthreads per chunk.
template<int K>
__device__ __forceinline__ void gemm_db(const float* __restrict__ Wg,
                                        const float* __restrict__ sAct,
                                        float (*__restrict__ sW)[32 * FEAT],
                                        ull acc[4][4],
                                        int tid, int lane, int fbase) {
    constexpr int NCH = (K + 31) / 32;
    float4 r0, r1;
    {   // chunk 0: load + commit to buf0 (sW unused since previous gemm's final sync)
        const float4* src = (const float4*)Wg;
        constexpr int lim0 = (K < 32 ? K : 32) * 32;
        float4* dst = (float4*)sW[0];
        if (tid < lim0)       { r0 = src[tid];       dst[tid] = r0; }
        if (tid + 512 < lim0) { r1 = src[tid + 512]; dst[tid + 512] = r1; }
    }
    if (NCH > 1) {  // prefetch chunk 1 into regs
        const float4* src = (const float4*)(Wg + 32 * FEAT);
        const int lim = ((K - 32 < 32) ? (K - 32) : 32) * 32;
        if (tid < lim)       r0 = src[tid];
        if (tid + 512 < lim) r1 = src[tid + 512];
    }
    #pragma unroll 1
    for (int c = 0; c < NCH; c++) {
        __syncthreads();  // chunk c committed & visible; buf[(c+1)&1] free to overwrite
        if (c + 1 < NCH) {  // commit chunk c+1 (regs -> other buffer) during compute window
            const int lim = (((K - (c + 1) * 32) < 32) ? (K - (c + 1) * 32) : 32) * 32;
            float4* dst = (float4*)sW[(c + 1) & 1];
            if (tid < lim)       dst[tid] = r0;
            if (tid + 512 < lim) dst[tid + 512] = r1;
        }
        if (c + 2 < NCH) {  // prefetch chunk c+2
            const float4* src = (const float4*)(Wg + (c + 2) * 32 * FEAT);
            const int lim = (((K - (c + 2) * 32) < 32) ? (K - (c + 2) * 32) : 32) * 32;
            if (tid < lim)       r0 = src[tid];
            if (tid + 512 < lim) r1 = src[tid + 512];
        }
        const int k0 = c * 32;
        const int rows = (K - k0 < 32) ? (K - k0) : 32;
        const float* w = sW[c & 1];
        #pragma unroll 4
        for (int kk = 0; kk < rows; kk++) {
            const float* arow = sAct + (k0 + kk) * TPAIR + lane;
            float a0 = arow[0], a1 = arow[32], a2 = arow[64], a3 = arow[96];
            ull av0 = pack2(a0, a0), av1 = pack2(a1, a1);
            ull av2 = pack2(a2, a2), av3 = pack2(a3, a3);
            const ulonglong2* wr = (const ulonglong2*)(w + kk * FEAT + fbase);
            ulonglong2 wA = wr[0], wB = wr[1];
            fma2(acc[0][0], av0, wA.x); fma2(acc[0][1], av0, wA.y);
            fma2(acc[0][2], av0, wB.x); fma2(acc[0][3], av0, wB.y);
            fma2(acc[1][0], av1, wA.x); fma2(acc[1][1], av1, wA.y);
            fma2(acc[1][2], av1, wB.x); fma2(acc[1][3], av1, wB.y);
            fma2(acc[2][0], av2, wA.x); fma2(acc[2][1], av2, wA.y);
            fma2(acc[2][2], av2, wB.x); fma2(acc[2][3], av2, wB.y);
            fma2(acc[3][0], av3, wA.x); fma2(acc[3][1], av3, wA.y);
            fma2(acc[3][2], av3, wB.x); fma2(acc[3][3], av3, wB.y);
        }
    }
    __syncthreads();  // protect act buffers + sW before next stage
}

// relu(acc + bias) -> dst in k-major layout dst[f][p]
__device__ __forceinline__ void epilogue(ull acc[4][4],
                                         const float* __restrict__ bias,
                                         float* __restrict__ dst, int lane, int fbase) {
    #pragma unroll
    for (int t = 0; t < 4; t++) {
        int f = fbase + 2 * t;
        float bx = bias[f], by = bias[f + 1];
        #pragma unroll
        for (int q = 0; q < 4; q++) {
            float2 v = unpack2(acc[q][t]);
            int p = lane + 32 * q;
            dst[f * TPAIR + p]       = fmaxf(v.x + bx, 0.f);
            dst[(f + 1) * TPAIR + p] = fmaxf(v.y + by, 0.f);
        }
    }
}

__device__ __forceinline__ void zero_acc(ull acc[4][4]) {
    #pragma unroll
    for (int q = 0; q < 4; q++)
        #pragma unroll
        for (int t = 0; t < 4; t++) acc[q][t] = 0ull;
}

__global__ void __launch_bounds__(NTHREADS, 1)
fused_kernel(const int* __restrict__ aa, const int* __restrict__ res_nb,
             const int* __restrict__ chain_nb, const float* __restrict__ pos,
             const float* __restrict__ mask,
             const float* __restrict__ dw1, const float* __restrict__ db1,
             const float* __restrict__ dw2, const float* __restrict__ db2,
             const float* __restrict__ ow1, const float* __restrict__ ob1,
             const float* __restrict__ ow2, const float* __restrict__ ob2,
             const float* __restrict__ ow3, const float* __restrict__ ob3,
             float* __restrict__ outp) {
    extern __shared__ char smem_raw[];
    Smem& s = *reinterpret_cast<Smem*>(smem_raw);
    const int tid = threadIdx.x;
    const int warp = tid >> 5, lane = tid & 31;
    const int fbase = warp * 8;
    const int bid = blockIdx.x;
    const int n  = bid >> 9;                 // 32*16 tiles per batch
    const int i0 = ((bid >> 4) & 31) * 8;
    const int j0 = (bid & 15) * 16;

    // ---- phase 0: cooperative loads (strided, full coverage) ----
    {
        const float* pbI = pos + (size_t)(n * LRES + i0) * NATOM * 3;
        const float* pbJ = pos + (size_t)(n * LRES + j0) * NATOM * 3;
        for (int idx = tid; idx < 8 * NATOM * 3; idx += NTHREADS)  s.posI[idx] = pbI[idx];
        for (int idx = tid; idx < 16 * NATOM * 3; idx += NTHREADS) s.posJ[idx] = pbJ[idx];
        const float* mbI = mask + (size_t)(n * LRES + i0) * NATOM;
        const float* mbJ = mask + (size_t)(n * LRES + j0) * NATOM;
        for (int idx = tid; idx < 8 * NATOM; idx += NTHREADS)  s.maskI[idx] = mbI[idx];
        for (int idx = tid; idx < 16 * NATOM; idx += NTHREADS) s.maskJ[idx] = mbJ[idx];
        if (tid < 8) {
            s.aaI[tid]  = aa[n * LRES + i0 + tid];
            s.resI[tid] = res_nb[n * LRES + i0 + tid];
            s.chI[tid]  = chain_nb[n * LRES + i0 + tid];
        }
        if (tid >= 32 && tid < 48) {
            int t = tid - 32;
            s.aaJ[t]  = aa[n * LRES + j0 + t];
            s.resJ[t] = res_nb[n * LRES + j0 + t];
            s.chJ[t]  = chain_nb[n * LRES + j0 + t];
        }
        if (tid >= 64 && tid < 192) {
            int t = tid - 64;
            s.b1[t] = db1[t]; s.b2[t] = db2[t]; s.b3[t] = ob1[t];
            s.b4[t] = ob2[t]; s.b5[t] = ob3[t];
        }
    }
    __syncthreads();

    // ---- phase 0b: per-pair meta + dihedral angular codes (k-major) ----
    if (tid < TPAIR) {
        int ii = tid >> 4, jj = tid & 15;
        s.aap[tid] = s.aaI[ii] * MAXAA + s.aaJ[jj];
        int r = s.resI[ii] - s.resJ[jj];
        s.rel[tid] = min(max(r, -32), 32) + 32;
        s.sc[tid] = (s.chI[ii] == s.chJ[jj]) ? 1.f : 0.f;
        s.mp[tid] = s.maskI[ii * NATOM + 1] * s.maskJ[jj * NATOM + 1];   // CA masks
        const float* dh = &g_dihed[((size_t)(n * LRES + i0 + ii) * LRES + (j0 + jj)) * 2];
        float phi = dh[0], psi = dh[1];
        const float FRQ[6] = {1.f, 2.f, 3.f, 1.f, 0.5f, 1.f / 3.f};
        s.dcodeK[0 * TPAIR + tid]  = phi;
        s.dcodeK[13 * TPAIR + tid] = psi;
        #pragma unroll
        for (int t = 0; t < 6; t++) {
            float sv, cv;
            sincosf(phi * FRQ[t], &sv, &cv);
            s.dcodeK[(1 + t) * TPAIR + tid]  = sv;
            s.dcodeK[(7 + t) * TPAIR + tid]  = cv;
            sincosf(psi * FRQ[t], &sv, &cv);
            s.dcodeK[(14 + t) * TPAIR + tid] = sv;
            s.dcodeK[(20 + t) * TPAIR + tid] = cv;
        }
    }
    __syncthreads();

    // ---- phase 1: masked gaussian distance features, k-major G[m][p] ----
    for (int idx = tid; idx < TPAIR * MPAIR; idx += NTHREADS) {
        int m = idx >> 7;
        int pp = idx & (TPAIR - 1);
        int a = m / NATOM;
        int b = m - a * NATOM;
        int ii = pp >> 4, jj = pp & 15;
        float dx = s.posI[ii * 42 + a * 3 + 0] - s.posJ[jj * 42 + b * 3 + 0];
        float dy = s.posI[ii * 42 + a * 3 + 1] - s.posJ[jj * 42 + b * 3 + 1];
        float dz = s.posI[ii * 42 + a * 3 + 2] - s.posJ[jj * 42 + b * 3 + 2];
        float ss = dx * dx + dy * dy + dz * dz;        // (10*d)^2
        float cc = g_softc[s.aap[pp] * MPAIR + m];
        float g = __expf(-cc * ss * 0.01f) * (s.maskI[ii * NATOM + a] * s.maskJ[jj * NATOM + b]);
        s.bufG[idx] = g;
    }
    // gemm's first __syncthreads covers bufG visibility

    ull acc[4][4];

    // ---- stage 1: h1 = relu(G @ dist_w1 + b1) -> bufB ----
    zero_acc(acc);
    gemm_db<MPAIR>(dw1, s.bufG, s.sW, acc, tid, lane, fbase);
    epilogue(acc, s.b1, s.bufB, lane, fbase);

    // ---- stage 2: fd = relu(h1 @ dist_w2 + b2) -> bufG rows 0..127 ----
    zero_acc(acc);
    gemm_db<FEAT>(dw2, s.bufB, s.sW, acc, tid, lane, fbase);
    epilogue(acc, s.b2, s.bufG, lane, fbase);
    // append dihedral codes as act rows 128..153 (visible by stage-3 gemm's first sync)
    for (int idx = tid; idx < 26 * TPAIR; idx += NTHREADS)
        s.bufG[FEAT * TPAIR + idx] = s.dcodeK[idx];

    // ---- stage 3: h = relu(preA + sc*preR + [fd;dihed] @ ow1[256:410] + ob1) -> bufB ----
    #pragma unroll
    for (int q = 0; q < 4; q++) {
        int p = lane + 32 * q;
        int ap = s.aap[p], rl = s.rel[p];
        float scv = s.sc[p];
        const float4* A4 = (const float4*)&g_preA[ap * FEAT + fbase];
        const float4* R4 = (const float4*)&g_preR[rl * FEAT + fbase];
        float4 a0 = A4[0], a1 = A4[1], r0 = R4[0], r1 = R4[1];
        acc[q][0] = pack2(a0.x + scv * r0.x, a0.y + scv * r0.y);
        acc[q][1] = pack2(a0.z + scv * r0.z, a0.w + scv * r0.w);
        acc[q][2] = pack2(a1.x + scv * r1.x, a1.y + scv * r1.y);
        acc[q][3] = pack2(a1.z + scv * r1.z, a1.w + scv * r1.w);
    }
    gemm_db<K3>(ow1 + 256 * FEAT, s.bufG, s.sW, acc, tid, lane, fbase);
    epilogue(acc, s.b3, s.bufB, lane, fbase);

    // ---- stage 4: h = relu(h @ out_w2 + ob2) -> bufG ----
    zero_acc(acc);
    gemm_db<FEAT>(ow2, s.bufB, s.sW, acc, tid, lane, fbase);
    epilogue(acc, s.b4, s.bufG, lane, fbase);

    // ---- stage 5: out = (h @ out_w3 + ob3) * mask_pair -> global ----
    zero_acc(acc);
    gemm_db<FEAT>(ow3, s.bufG, s.sW, acc, tid, lane, fbase);
    #pragma unroll
    for (int q = 0; q < 4; q++) {
        int p = lane + 32 * q;
        int ii = p >> 4, jj = p & 15;
        float mpv = s.mp[p];
        float* orow = outp + ((((size_t)n * LRES + (i0 + ii)) * LRES + (j0 + jj)) * FEAT + fbase);
        float2 v0 = unpack2(acc[q][0]);
        float2 v1 = unpack2(acc[q][1]);
        float2 v2 = unpack2(acc[q][2]);
        float2 v3 = unpack2(acc[q][3]);
        float4 o0 = make_float4((v0.x + s.b5[fbase])     * mpv,
                                (v0.y + s.b5[fbase + 1]) * mpv,
                                (v1.x + s.b5[fbase + 2]) * mpv,
                                (v1.y + s.b5[fbase + 3]) * mpv);
        float4 o1 = make_float4((v2.x + s.b5[fbase + 4]) * mpv,
                                (v2.y + s.b5[fbase + 5]) * mpv,
                                (v3.x + s.b5[fbase + 6]) * mpv,
                                (v3.y + s.b5[fbase + 7]) * mpv);
        *(float4*)&orow[0] = o0;
        *(float4*)&orow[4] = o1;
    }
}

// ---------------- launch ----------------
extern "C" void kernel_launch(void* const* d_in, const int* in_sizes, int n_in,
                              void* d_out, int out_size) {
    const int*   aa        = (const int*)  d_in[0];
    const int*   res_nb    = (const int*)  d_in[1];
    const int*   chain_nb  = (const int*)  d_in[2];
    const float* pos       = (const float*)d_in[3];
    const float* mask      = (const float*)d_in[4];
    const float* aap_embed = (const float*)d_in[5];
    const float* rel_embed = (const float*)d_in[6];
    const float* distcoef  = (const float*)d_in[7];
    const float* dw1 = (const float*)d_in[8];
    const float* db1 = (const float*)d_in[9];
    const float* dw2 = (const float*)d_in[10];
    const float* db2 = (const float*)d_in[11];
    const float* ow1 = (const float*)d_in[12];
    const float* ob1 = (const float*)d_in[13];
    const float* ow2 = (const float*)d_in[14];
    const float* ob2 = (const float*)d_in[15];
    const float* ow3 = (const float*)d_in[16];
    const float* ob3 = (const float*)d_in[17];
    float* outp = (float*)d_out;

    cudaFuncSetAttribute(fused_kernel, cudaFuncAttributeMaxDynamicSharedMemorySize,
                         (int)sizeof(Smem));

    softc_kernel<<<(NAPAIR * MPAIR + 255) / 256, 256>>>(distcoef);
    pretab_kernel<<<NAPAIR + NREL, 128>>>(aap_embed, rel_embed, ow1);
    dihed_kernel<<<(NBATCH * LRES * LRES) / 256, 256>>>(pos);
    fused_kernel<<<NBATCH * 32 * 16, NTHREADS, sizeof(Smem)>>>(
        aa, res_nb, chain_nb, pos, mask,
        dw1, db1, dw2, db2, ow1, ob1, ow2, ob2, ow3, ob3, outp);
}